// round 10
// baseline (speedup 1.0000x reference)
#include <cuda_runtime.h>

#define B_   32
#define M_   64
#define A_   8400
#define TK   9
#define NC   80
#define EPSF 1e-9f

// Scratch (allocation-free). Packed per-anchor tag: bits[31:16] = positive
// count, bits[15:0] = sum of (m+1). count<=64, sum(m+1)<=4096 -> no overflow
// between fields; when count==1 the low half is exactly m+1.
// INVARIANT: zero at module load (CUDA zero-init), and the assign kernel
// re-zeroes each element after consuming it, so every launch (and every graph
// replay) starts from zero -> no init kernel needed.
__device__ int g_tag[B_ * A_];

__device__ __forceinline__ float iou_box(float gx1, float gy1, float gx2, float gy2,
                                         float bx1, float by1, float bx2, float by2) {
    // matches reference _iou: b1 = gt, b2 = other; denom = a1 + a2 - overlap + EPS
    float ix1 = fmaxf(gx1, bx1), iy1 = fmaxf(gy1, by1);
    float ix2 = fminf(gx2, bx2), iy2 = fminf(gy2, by2);
    float ov  = fmaxf(ix2 - ix1, 0.f) * fmaxf(iy2 - iy1, 0.f);
    float a1  = fmaxf(gx2 - gx1, 0.f) * fmaxf(gy2 - gy1, 0.f);
    float a2  = fmaxf(bx2 - bx1, 0.f) * fmaxf(by2 - by1, 0.f);
    return ov / (a1 + a2 - ov + EPSF);
}

// One WARP per (b,m). Anchors are regular grids, so the top-9-by-center-distance
// per FPN level is contained in the 5x5 grid window around the gt center
// (9th-nearest lattice distance <= 1.581*stride < 2.0*stride = min excluded
// distance). Selection = 9 rounds of warp-min over u64 (d2,idx) keys — exact
// lax.top_k tie-break (d2-order refines sqrt-order; only the SET is consumed).
// thr = mean + std(ddof=1) over the 27 candidate IoUs, sequential order r=0..26
// (bit-identical to the R4/R5 passing kernels). Positives scatter one packed atomic.
__global__ void __launch_bounds__(256) atss_topk_kernel(
    const float* __restrict__ anchors,    // [A,4]
    const float* __restrict__ gt_bboxes,  // [B,M,4]
    const float* __restrict__ pad_mask)   // [B,M,1]
{
    const int warp = threadIdx.x >> 5;
    const int lane = threadIdx.x & 31;
    const int wid  = blockIdx.x * 8 + warp;   // (b,m) flat, 2048 total
    const int b = wid >> 6;
    const int m = wid & 63;

    if (pad_mask[wid] <= 0.f) return;         // warp-uniform

    const float4 g = ((const float4*)gt_bboxes)[wid];
    const float gcx = (g.x + g.z) * 0.5f;
    const float gcy = (g.y + g.w) * 0.5f;

    const int   FS[3]   = {80, 40, 20};
    const float INV[3]  = {0.125f, 0.0625f, 0.03125f};  // 1/stride (exact pow2)
    const int   BASE[3] = {0, 6400, 8000};

    int my_win = 0;          // lane r (< 27) ends up holding winner lvl*9 + r
    bool have_win = false;

    #pragma unroll
    for (int lvl = 0; lvl < 3; lvl++) {
        const int fs = FS[lvl];
        const int base = BASE[lvl];
        int jx0 = (int)floorf(gcx * INV[lvl] - 0.5f) - 2;
        int iy0 = (int)floorf(gcy * INV[lvl] - 0.5f) - 2;
        jx0 = min(max(jx0, 0), fs - 5);
        iy0 = min(max(iy0, 0), fs - 5);

        unsigned long long key = ~0ull;
        if (lane < 25) {
            const int idx = base + (iy0 + lane / 5) * fs + (jx0 + lane % 5);
            float4 ab = ((const float4*)anchors)[idx];
            float acx = (ab.x + ab.z) * 0.5f;
            float acy = (ab.y + ab.w) * 0.5f;
            float dx = gcx - acx, dy = gcy - acy;
            float d2 = dx * dx + dy * dy;       // nonneg -> bit pattern is order-preserving
            key = ((unsigned long long)__float_as_uint(d2) << 32) | (unsigned)idx;
        }

        #pragma unroll
        for (int r = 0; r < TK; r++) {
            unsigned long long mn = key;
            #pragma unroll
            for (int off = 16; off; off >>= 1) {
                unsigned long long o = __shfl_xor_sync(0xffffffffu, mn, off);
                if (o < mn) mn = o;
            }
            if (key == mn) key = ~0ull;         // winner drops out (keys unique)
            if (lane == lvl * TK + r) { my_win = (int)(mn & 0xffffffffu); have_win = true; }
        }
    }

    // IoU of the 27 winners with the gt box
    float my_iou = 0.f;
    float4 ab = make_float4(0.f, 0.f, 0.f, 0.f);
    if (have_win) {
        ab = ((const float4*)anchors)[my_win];
        my_iou = iou_box(g.x, g.y, g.z, g.w, ab.x, ab.y, ab.z, ab.w);
    }

    // mean + std (ddof=1), sequential order r = 0..26 (matches prior passing kernel)
    float mean = 0.f;
    #pragma unroll
    for (int r = 0; r < 27; r++) mean += __shfl_sync(0xffffffffu, my_iou, r);
    mean *= (1.f / 27.f);
    float var = 0.f;
    #pragma unroll
    for (int r = 0; r < 27; r++) {
        float v = __shfl_sync(0xffffffffu, my_iou, r) - mean;
        var += v * v;
    }
    const float thr = mean + sqrtf(var * (1.f / 26.f));

    if (have_win && my_iou > thr) {
        float acx = (ab.x + ab.z) * 0.5f;
        float acy = (ab.y + ab.w) * 0.5f;
        float lmin = fminf(fminf(acx - g.x, acy - g.y), fminf(g.z - acx, g.w - acy));
        if (lmin > EPSF) {                      // is_in_gts (strict > EPS)
            atomicAdd(&g_tag[b * A_ + my_win], 0x10000 + m + 1);
        }
    }
}

// Fused finalize: one block = 256 anchors of one batch image.
// Phase 1 (thread-per-anchor): consume + re-zero g_tag, resolve multi-assignment
// (argmax anchor-IoU over all 64 gts, first-max ties), write labels + bboxes,
// stash (label, sval) in shared.
// Phase 2: stream COMPLETE one-hot score rows as coalesced float4 stores —
// scores are written exactly once, no separate zero-fill pass.
__global__ void __launch_bounds__(256) atss_assign_kernel(
    const float* __restrict__ anchors,    // [A,4]
    const int*   __restrict__ gt_labels,  // [B,M]
    const float* __restrict__ gt_bboxes,  // [B,M,4]
    const float* __restrict__ pred,       // [B,A,4]
    const int*   __restrict__ bg_ptr,     // [1] or null
    float*       __restrict__ out)
{
    const int b  = blockIdx.y;
    const int t  = threadIdx.x;
    const int a0 = blockIdx.x * 256;
    const int a  = a0 + t;

    __shared__ float4 s_gt[M_];
    __shared__ int    s_lab[M_];
    __shared__ int    s_alab[256];   // assigned label, or -1 when score row is all-zero
    __shared__ float  s_sval[256];

    if (t < M_) {
        s_gt[t]  = ((const float4*)gt_bboxes)[b * M_ + t];
        s_lab[t] = gt_labels[b * M_ + t];
    }
    __syncthreads();

    const long long OFF1 = (long long)B_ * A_;            // bboxes offset
    const long long OFF2 = OFF1 + (long long)B_ * A_ * 4; // scores offset

    if (a < A_) {
        const long long ba = (long long)b * A_ + a;
        const int bg = bg_ptr ? bg_ptr[0] : NC;

        const int tag = g_tag[ba];
        g_tag[ba] = 0;                          // restore zero invariant for next replay
        const int cnt = tag >> 16;
        int asg = (cnt == 1) ? (tag & 0xffff) - 1 : 0;

        if (cnt > 1) {
            // mask_multi -> is_max_iou column: argmax over m of anchor-iou, first-max ties
            float4 ab = ((const float4*)anchors)[a];
            float best = -1.f; int bm = 0;
            #pragma unroll 4
            for (int mm = 0; mm < M_; mm++) {
                float4 gg = s_gt[mm];
                float v = iou_box(gg.x, gg.y, gg.z, gg.w, ab.x, ab.y, ab.z, ab.w);
                if (v > best) { best = v; bm = mm; }
            }
            asg = bm;
        }

        int   label = bg;
        float sval  = 0.f;
        if (cnt > 0) {
            label = s_lab[asg];
            float4 p = ((const float4*)pred)[ba];
            float4 gg = s_gt[asg];
            sval = iou_box(gg.x, gg.y, gg.z, gg.w, p.x, p.y, p.z, p.w);
        }

        out[ba] = (float)label;                  // assigned_labels (as f32)
        ((float4*)(out + OFF1))[ba] = s_gt[asg]; // assigned_bboxes (gt[0] when bg)

        s_alab[t] = (cnt > 0 && label >= 0 && label < NC) ? label : -1;
        s_sval[t] = sval;
    }
    __syncthreads();

    // Phase 2: coalesced full score rows. nA anchors -> nA*20 float4 stores.
    int nA = A_ - a0; if (nA > 256) nA = 256;
    const int nvec = nA * (NC / 4);
    float4* srow = (float4*)(out + OFF2 + ((long long)b * A_ + a0) * NC);
    for (int i = t; i < nvec; i += 256) {
        const int al = i / (NC / 4);             // local anchor
        const int c4 = (i - al * (NC / 4)) * 4;  // first class of this vector
        const int lab = s_alab[al];
        float4 v = make_float4(0.f, 0.f, 0.f, 0.f);
        const int d = lab - c4;                  // one-hot slot within this float4?
        if ((unsigned)d < 4u) {
            const float s = s_sval[al];
            if (d == 0) v.x = s; else if (d == 1) v.y = s;
            else if (d == 2) v.z = s; else v.w = s;
        }
        srow[i] = v;
    }
}

extern "C" void kernel_launch(void* const* d_in, const int* in_sizes, int n_in,
                              void* d_out, int out_size) {
    const float* anchors   = (const float*)d_in[0];
    const int*   gt_labels = (const int*)d_in[1];
    const float* gt_bboxes = (const float*)d_in[2];
    const float* pad_mask  = (const float*)d_in[3];
    const float* pred      = (const float*)d_in[4];
    const int*   bg_ptr    = (n_in > 5) ? (const int*)d_in[5] : nullptr;
    float* out = (float*)d_out;

    atss_topk_kernel<<<(B_ * M_) / 8, 256>>>(anchors, gt_bboxes, pad_mask);
    atss_assign_kernel<<<dim3((A_ + 255) / 256, B_), 256>>>(
        anchors, gt_labels, gt_bboxes, pred, bg_ptr, out);
}